// round 14
// baseline (speedup 1.0000x reference)
#include <cuda_runtime.h>
#include <cstdint>

#define DIMC 384
#define G     192        // channels per CTA (cluster-2 covers 384)
#define NP    49
#define CSTRIDE 116      // floats per channel in SMEM: 7 rows x 16 + 4 pad
#define NT    672        // 21 warps
#define CHUNK_F4 1792    // 64 channels x 28 f4 per chunk

#define CP_ASYNC_CG(dst, src) \
    asm volatile("cp.async.cg.shared.global [%0], [%1], 16;" \
                 :: "r"(dst), "l"(src) : "memory")
#define CP_COMMIT() asm volatile("cp.async.commit_group;" ::: "memory")
#define CP_WAIT(N)  asm volatile("cp.async.wait_group %0;" :: "n"(N) : "memory")

// Phase-2 inner body: 32-channel partial dot with s_aw, two accumulators.
#define PL_BODY(CBASE)                                                        \
    {                                                                         \
        const int cb0 = (CBASE);                                              \
        float a0 = 0.0f, a1 = 0.0f;                                           \
        _Pragma("unroll")                                                     \
        for (int i = 0; i < 32; i += 2) {                                     \
            a0 = fmaf(s_raw[(cb0 + i)     * CSTRIDE + off], s_aw[cb0 + i], a0); \
            a1 = fmaf(s_raw[(cb0 + i + 1) * CSTRIDE + off], s_aw[cb0 + i + 1], a1); \
        }                                                                     \
        s_pl[cb][slot] = a0 + a1;                                             \
    }

// Phase-4 body with compile-time window shift S (s is uniform 0 or 2).
#define P4BODY(S)                                                             \
    _Pragma("unroll")                                                         \
    for (int r = 0; r < 7; ++r) {                                             \
        float4 q0 = ch4[r * 4],     q1 = ch4[r * 4 + 1];                      \
        float4 q2 = ch4[r * 4 + 2], q3 = ch4[r * 4 + 3];                      \
        float v[16] = {q0.x, q0.y, q0.z, q0.w, q1.x, q1.y, q1.z, q1.w,        \
                       q2.x, q2.y, q2.z, q2.w, q3.x, q3.y, q3.z, q3.w};       \
        _Pragma("unroll")                                                     \
        for (int x = 0; x < 7; ++x) {                                         \
            acc0 = fmaf(v[(S) + x],     s_attn[2 * (7 * r + x)],     acc0);   \
            acc1 = fmaf(v[(S) + 7 + x], s_attn[2 * (7 * r + x) + 1], acc1);   \
        }                                                                     \
    }

__global__ void __launch_bounds__(NT, 2) __cluster_dims__(2, 1, 1)
attn_ds_kernel(
    const float* __restrict__ hr,   // (8, 384, 112, 112)
    const float* __restrict__ du,   // (8, 16, 16, 1)
    const float* __restrict__ aw,   // (384,)
    const float* __restrict__ ab,   // (1,)
    const float* __restrict__ wt,   // (7,7) -> 49
    const float* __restrict__ bt,   // (7,7) -> 49
    float* __restrict__ out)        // (8, 384, 16, 16)
{
    extern __shared__ float s_raw[];          // [192][116] = 89088 B
    __shared__ float s_pl[6][98];             // phase-2 sub-partials per 32-ch block
    __shared__ float s_red[2][98];            // [0]=own, [1]=peer-written
    __shared__ float s_attn[98];              // attn weights [2p + w]
    __shared__ float s_aw[G];

    const int tid  = threadIdx.x;
    const int lane = tid & 31;
    const int wid  = tid >> 5;
    const int rank = blockIdx.x & 1;          // channel half
    const int grp  = blockIdx.x >> 1;         // (b*16+h)*8 + pp
    const int pp   = grp & 7;                 // pixel-pair: pixels 2pp, 2pp+1
    const int strip= grp >> 3;                // b*16 + h
    const int b = strip >> 4, h = strip & 15;
    const int c0 = rank * G;
    const int s  = 2 * (pp & 1);              // uniform window shift (0 or 2)
    const int q4 = (14 * pp - s) >> 2;        // f4 offset of aligned window in row

    if (tid < G) s_aw[tid] = aw[c0 + tid];

    const float4* hr4 = (const float4*)hr;
    const uint32_t sbase = (uint32_t)__cvta_generic_to_shared(s_raw);

    // ---- Load: 3 chunks x 64 channels, cp.async.cg of aligned 64B windows ----
    // Per chunk: 1792 f4; idx -> c_loc = (idx>>2)/7 (magic 9363), r, fc.
    // src row = (7h + r); window start q4; dst = (64k+c_loc)*116 + r*16 + fc*4.
    #pragma unroll
    for (int k = 0; k < 3; ++k) {
        #pragma unroll
        for (int i = 0; i < 3; ++i) {
            unsigned idx = (unsigned)tid + i * NT;
            if (i < 2 || tid < CHUNK_F4 - 2 * NT) {      // 1792 = 2*672 + 448
                unsigned t2 = idx >> 2;
                unsigned cl = (t2 * 9363u) >> 16;        // t2/7
                unsigned rr = t2 - 7u * cl;
                unsigned fc = idx & 3u;
                const float4* src = hr4
                    + ((size_t)(b * DIMC + c0 + 64 * k + cl)) * 3136
                    + (size_t)(7 * h + rr) * 28 + q4 + fc;
                CP_ASYNC_CG(sbase + ((64 * k + cl) * CSTRIDE + rr * 16 + fc * 4) * 4u,
                            src);
            }
        }
        CP_COMMIT();
    }

    // ---- Phase 2, progressive: thread t<588 -> (cb = t/98, slot = t%98) ----
    // slot = 2p + w; off = r*16 + s + 7w + x (r = p/7, x = p%7).
    int cb = 0, slot = 0, off = 0;
    const bool act = tid < 588;
    if (act) {
        cb   = (tid * 669) >> 16;             // t/98, exact for t < 588
        slot = tid - 98 * cb;
        int p = slot >> 1, w = slot & 1;
        int r = (p * 9363) >> 16;
        int x = p - 7 * r;
        off = r * 16 + s + 7 * w + x;
    }

    CP_WAIT(2);  __syncthreads();             // channels [0,64) visible
    if (act && cb < 2)              PL_BODY(cb * 32)
    CP_WAIT(1);  __syncthreads();             // channels [64,128) visible
    if (act && cb >= 2 && cb < 4)   PL_BODY(cb * 32)
    CP_WAIT(0);  __syncthreads();             // channels [128,192) visible
    if (act && cb >= 4)             PL_BODY(cb * 32)
    __syncthreads();

    // ---- Combine 6 sub-partials; push to the single peer CTA ----
    if (tid < 98) {
        float t = s_pl[0][tid] + s_pl[1][tid] + s_pl[2][tid]
                + s_pl[3][tid] + s_pl[4][tid] + s_pl[5][tid];
        s_red[0][tid] = t;
        uint32_t loc = (uint32_t)__cvta_generic_to_shared(&s_red[1][tid]);
        uint32_t rem;
        asm ("mapa.shared::cluster.u32 %0, %1, %2;" : "=r"(rem) : "r"(loc), "r"(rank ^ 1));
        asm volatile("st.shared::cluster.f32 [%0], %1;" :: "r"(rem), "f"(t) : "memory");
    }
    asm volatile("barrier.cluster.arrive.aligned;" ::: "memory");
    asm volatile("barrier.cluster.wait.aligned;"   ::: "memory");

    // ---- Softmax: warp wid handles pixel w = wid (2 pixels) ----
    if (wid < 2) {
        const int w = wid;
        const float m   = (du[(strip << 4) + 2 * pp + w] > 0.2f) ? 1.0f : 0.0f;
        const float a0c = ab[0];
        const int p1 = lane + 32;
        float l0 = (s_red[0][2 * lane + w] + s_red[1][2 * lane + w] + a0c)
                   * m * wt[lane] + bt[lane];
        float l1 = (p1 < NP)
                 ? (s_red[0][2 * p1 + w] + s_red[1][2 * p1 + w] + a0c)
                   * m * wt[p1] + bt[p1]
                 : -1e30f;
        float mx = fmaxf(l0, l1);
        #pragma unroll
        for (int o = 16; o > 0; o >>= 1)
            mx = fmaxf(mx, __shfl_xor_sync(0xffffffffu, mx, o));
        float e0 = __expf(l0 - mx);
        float e1 = (p1 < NP) ? __expf(l1 - mx) : 0.0f;
        float sm = e0 + e1;
        #pragma unroll
        for (int o = 16; o > 0; o >>= 1)
            sm += __shfl_xor_sync(0xffffffffu, sm, o);
        const float inv = 1.0f / sm;
        s_attn[2 * lane + w] = e0 * inv;
        if (p1 < NP) s_attn[2 * p1 + w] = e1 * inv;
    }
    __syncthreads();

    // ---- Phase 4: thread = channel; LDS.128 rows (granule stride 29, odd ->
    // conflict-free); both pixels accumulated, one float2 store. ----
    if (tid < G) {
        const float4* ch4 = (const float4*)(s_raw + tid * CSTRIDE);  // 464B stride
        float acc0 = 0.0f, acc1 = 0.0f;
        if (s == 0) { P4BODY(0) } else { P4BODY(2) }
        size_t o = (((size_t)(b * DIMC + c0 + tid)) << 8) + (h << 4) + 2 * pp;
        __stcg(reinterpret_cast<float2*>(out + o), make_float2(acc0, acc1));
    }
}

extern "C" void kernel_launch(void* const* d_in, const int* in_sizes, int n_in,
                              void* d_out, int out_size)
{
    const float* hr = (const float*)d_in[0];  // hr_feats
    // d_in[1] = guidance (unused, zeros)
    const float* du = (const float*)d_in[2];  // dropout_u
    const float* aw = (const float*)d_in[3];
    const float* ab = (const float*)d_in[4];
    const float* wt = (const float*)d_in[5];
    const float* bt = (const float*)d_in[6];
    float* out = (float*)d_out;

    const size_t smem = (size_t)G * CSTRIDE * sizeof(float);  // 89088 B
    cudaFuncSetAttribute(attn_ds_kernel,
                         cudaFuncAttributeMaxDynamicSharedMemorySize, (int)smem);
    // 128 strips x 8 pixel-pairs x 2-CTA clusters = 2048 CTAs; cluster-2
    // packs 148 SMs perfectly (no cluster-4 stranding), 2 CTAs/SM.
    attn_ds_kernel<<<2048, NT, smem>>>(hr, du, aw, ab, wt, bt, out);
}